// round 15
// baseline (speedup 1.0000x reference)
#include <cuda_runtime.h>
#include <cuda_fp16.h>
#include <cstdint>
#include <math.h>

#define BB 4
#define SS 8192
#define HH 768
#define NH 12
#define HD 64
#define MM 64
#define NTOK (BB * SS)          // 32768
#define BHS (BB * NH)           // 48
#define EPSF 1e-6f

// ======================= helpers =======================
__device__ __forceinline__ uint32_t smem_u32(const void* p) {
    uint32_t a;
    asm("{ .reg .u64 t; cvta.to.shared.u64 t, %1; cvt.u32.u64 %0, t; }" : "=r"(a) : "l"(p));
    return a;
}

#define SWZ(o) ((o) ^ (((o) >> 3) & 0x70))

__device__ __forceinline__ void cpa16(uint32_t dst, const void* src) {
    asm volatile("cp.async.cg.shared.global [%0], [%1], 16;" :: "r"(dst), "l"(src));
}
#define CP_COMMIT() asm volatile("cp.async.commit_group;" ::: "memory")
#define CP_WAIT0()  asm volatile("cp.async.wait_group 0;" ::: "memory")
#define CP_WAIT1()  asm volatile("cp.async.wait_group 1;" ::: "memory")

__device__ __forceinline__ void ldsm4(uint32_t* r, uint32_t addr) {
    asm volatile("ldmatrix.sync.aligned.m8n8.x4.shared.b16 {%0,%1,%2,%3}, [%4];"
        : "=r"(r[0]), "=r"(r[1]), "=r"(r[2]), "=r"(r[3]) : "r"(addr));
}
// fp16 MMA, f32 accumulate
__device__ __forceinline__ void mma16816(float* c, const uint32_t* a, const uint32_t* b) {
    asm volatile("mma.sync.aligned.m16n8k16.row.col.f32.f16.f16.f32 "
        "{%0,%1,%2,%3}, {%4,%5,%6,%7}, {%8,%9}, {%0,%1,%2,%3};"
        : "+f"(c[0]), "+f"(c[1]), "+f"(c[2]), "+f"(c[3])
        : "r"(a[0]), "r"(a[1]), "r"(a[2]), "r"(a[3]), "r"(b[0]), "r"(b[1]));
}

__device__ __forceinline__ void split2(float v, __half& hi, __half& lo) {
    hi = __float2half_rn(v);
    lo = __float2half_rn(v - __half2float(hi));
}

// load a [rows x 64] half chunk (row -> 128B swizzled) via cp.async
__device__ __forceinline__ void cp_tile64(const __half* __restrict__ g, int row0,
                                          int ld, int kc0, uint32_t sbase, int tid, int rows) {
    int total = rows * 8;
    for (int i = tid; i < total; i += 256) {
        int r = i >> 3, j = i & 7;
        uint32_t bo = (uint32_t)(r * 128 + j * 16);
        cpa16(sbase + SWZ(bo), g + (size_t)(row0 + r) * ld + kc0 + j * 8);
    }
}

// ======================= scratch =======================
__device__ __half g_xhi[(size_t)NTOK * HH], g_xlo[(size_t)NTOK * HH];
__device__ __half g_wqph[(size_t)HH * HH];
__device__ __half g_wkph[(size_t)HH * HH];
__device__ __half g_wvth[(size_t)HH * HH];
__device__ __half g_woth[(size_t)HH * HH];
__device__ float  g_bqf[HH], g_bkf[HH];
__device__ __half g_qphi[(size_t)NTOK * HH];
__device__ __half g_kph[(size_t)BHS * SS * MM];
__device__ __half g_vh[(size_t)NTOK * HH];
__device__ float  g_kv[(size_t)BHS * MM * HD];
__device__ float  g_ksum[(size_t)BHS * MM];
__device__ __half g_kvxh[(size_t)BHS * 128 * 64];
__device__ __half g_ctxh[(size_t)NTOK * HH];

// ======================= preprocessing =======================
__global__ void split_f32_kernel(const float* __restrict__ x,
                                 __half* __restrict__ hi,
                                 __half* __restrict__ lo, size_t n2) {
    const float2* x2 = reinterpret_cast<const float2*>(x);
    __half2* h2 = reinterpret_cast<__half2*>(hi);
    __half2* l2 = reinterpret_cast<__half2*>(lo);
    for (size_t i = (size_t)blockIdx.x * blockDim.x + threadIdx.x; i < n2;
         i += (size_t)gridDim.x * blockDim.x) {
        float2 v = x2[i];
        __half hx, lx, hy, ly;
        split2(v.x, hx, lx);
        split2(v.y, hy, ly);
        h2[i] = __half2(hx, hy);
        l2[i] = __half2(lx, ly);
    }
}

// W[K=768][N=768] -> Wt[n][k] fp16 hi; z selects (Wv, Wo)
__global__ void wt_prep_kernel(const float* __restrict__ Wv, const float* __restrict__ Wo,
                               __half* __restrict__ hiV, __half* __restrict__ hiO) {
    const float* W = blockIdx.z ? Wo : Wv;
    __half* hi = blockIdx.z ? hiO : hiV;
    __shared__ float t[32][33];
    int bx = blockIdx.x * 32, by = blockIdx.y * 32;
    int x = threadIdx.x, y = threadIdx.y;   // block (32,8)
    #pragma unroll
    for (int i = 0; i < 32; i += 8)
        t[y + i][x] = W[(size_t)(by + y + i) * HH + bx + x];
    __syncthreads();
    #pragma unroll
    for (int i = 0; i < 32; i += 8) {
        size_t o = (size_t)(bx + y + i) * HH + by + x;
        hi[o] = __float2half_rn(t[x][y + i]);
    }
}

// Wt_fold[n=h*64+m][k=i] = sum_d W[i][h*64+d] * P[h][d][m]; 64 i-rows per block
__global__ void fold_w_kernel(const float* __restrict__ W, const float* __restrict__ P,
                              __half* __restrict__ hi) {
    int h = blockIdx.y;
    int i0 = blockIdx.x * 64;
    __shared__ float Ps[64][65];
    __shared__ float Ws[64][65];
    for (int t = threadIdx.x; t < 64 * 64; t += 256) {
        Ps[t >> 6][t & 63] = P[(size_t)h * 4096 + t];
        Ws[t >> 6][t & 63] = W[(size_t)(i0 + (t >> 6)) * HH + h * 64 + (t & 63)];
    }
    __syncthreads();
    for (int t = threadIdx.x; t < 64 * 64; t += 256) {
        int il = t >> 6, m = t & 63;
        float s = 0.f;
        #pragma unroll
        for (int d = 0; d < 64; d++) s = fmaf(Ws[il][d], Ps[d][m], s);
        hi[(size_t)(h * 64 + m) * HH + i0 + il] = __float2half_rn(s);
    }
}

// b_fold[h*64+m] = sum_d b[h*64+d] * P[h][d][m]; y selects (bq, bk)
__global__ void fold_b_kernel(const float* __restrict__ bq, const float* __restrict__ bk,
                              const float* __restrict__ P,
                              float* __restrict__ bqo, float* __restrict__ bko) {
    const float* b = blockIdx.y ? bk : bq;
    float* bout = blockIdx.y ? bko : bqo;
    int h = blockIdx.x, m = threadIdx.x;
    float s = 0.f;
    for (int d = 0; d < 64; d++)
        s = fmaf(b[h * 64 + d], P[(size_t)h * 4096 + d * 64 + m], s);
    bout[h * 64 + m] = s;
}

// kv [bh][m][d], ksum [bh][m] -> kvx [bh][n][k] (80 rows): n<64: kv[k][n]; n==64: ksum[k]; 65..79: 0
__global__ void kvx_prep_kernel(const float* __restrict__ kvf,
                                const float* __restrict__ ksum,
                                __half* __restrict__ hi) {
    int bh = blockIdx.x;
    for (int i = threadIdx.x; i < 80 * 64; i += 256) {
        int n = i >> 6, kk = i & 63;
        float v = 0.f;
        if (n < 64)       v = kvf[((size_t)bh * MM + kk) * HD + n];
        else if (n == 64) v = ksum[(size_t)bh * MM + kk];
        hi[(size_t)bh * 128 * 64 + i] = __float2half_rn(v);
    }
}

__global__ void zero_kernel(float* __restrict__ p, int n) {
    int i = blockIdx.x * blockDim.x + threadIdx.x;
    if (i < n) p[i] = 0.f;
}

// ======================= big GEMM: 256x128 CTA tile, 64x64 warp tile =======================
// NPASS=2: (a_hi + a_lo) * b_hi ; NPASS=1: a_hi * b_hi
// mode 0: fp32 + bias -> Cf.  mode 1: fp16 + bias -> Chi.
// mode 2: exp(...) fp16 -> Chi [tok][768].  mode 3: exp(...) fp16 -> Chi kp layout [bh][s][64].
#define SA_HI 0
#define SA_LO 32768
#define SB_HI 65536
#define STAGE 81920

template <int NPASS>
__global__ __launch_bounds__(256, 1)
void gemm_tc_kernel(const __half* __restrict__ Ahi, const __half* __restrict__ Alo,
                    const __half* __restrict__ Bhi,
                    const float* __restrict__ bias, float* __restrict__ Cf,
                    __half* __restrict__ Chi, int mode) {
    extern __shared__ char smem[];
    uint32_t sb = smem_u32(smem);
    int tid = threadIdx.x, wid = tid >> 5, lane = tid & 31;
    int row0 = blockIdx.y * 256, col0 = blockIdx.x * 128;
    int wm = (wid & 3) * 64, wn = (wid >> 2) * 64;

    float acc[4][8][4];
    #pragma unroll
    for (int a = 0; a < 4; a++)
        #pragma unroll
        for (int bq = 0; bq < 8; bq++)
            #pragma unroll
            for (int cq = 0; cq < 4; cq++) acc[a][bq][cq] = 0.f;

    // prologue: stage 0
    {
        cp_tile64(Ahi, row0, HH, 0, sb + SA_HI, tid, 256);
        if (NPASS == 2) cp_tile64(Alo, row0, HH, 0, sb + SA_LO, tid, 256);
        cp_tile64(Bhi, col0, HH, 0, sb + SB_HI, tid, 128);
        CP_COMMIT();
    }

    for (int c = 0; c < 12; c++) {
        int buf = c & 1;
        if (c + 1 < 12) {
            uint32_t sn = sb + (buf ^ 1) * STAGE;
            int kc = (c + 1) * 64;
            cp_tile64(Ahi, row0, HH, kc, sn + SA_HI, tid, 256);
            if (NPASS == 2) cp_tile64(Alo, row0, HH, kc, sn + SA_LO, tid, 256);
            cp_tile64(Bhi, col0, HH, kc, sn + SB_HI, tid, 128);
            CP_COMMIT();
            CP_WAIT1();
        } else {
            CP_WAIT0();
        }
        __syncthreads();

        uint32_t s0 = sb + buf * STAGE;
        #pragma unroll
        for (int ks = 0; ks < 4; ks++) {
            uint32_t bh2[4][4];
            int kb = ks * 32 + ((lane & 8) ? 16 : 0);
            #pragma unroll
            for (int q = 0; q < 4; q++) {
                int nr = wn + q * 16 + (lane & 7) + ((lane & 16) ? 8 : 0);
                ldsm4(bh2[q], s0 + SB_HI + SWZ((uint32_t)(nr * 128 + kb)));
            }
            #pragma unroll
            for (int im = 0; im < 4; im++) {
                int rowa = wm + im * 16 + (lane & 15);
                int ka = ks * 32 + ((lane & 16) ? 16 : 0);
                uint32_t ah[4], al[4];
                ldsm4(ah, s0 + SA_HI + SWZ((uint32_t)(rowa * 128 + ka)));
                if (NPASS == 2) ldsm4(al, s0 + SA_LO + SWZ((uint32_t)(rowa * 128 + ka)));
                #pragma unroll
                for (int in = 0; in < 8; in++) {
                    const uint32_t* bhp = &bh2[in >> 1][(in & 1) * 2];
                    mma16816(acc[im][in], ah, bhp);
                    if (NPASS == 2) mma16816(acc[im][in], al, bhp);
                }
            }
        }
        __syncthreads();
    }

    // stage accumulators to smem (256 x 128, stride 132)
    float* fs = reinterpret_cast<float*>(smem);
    #pragma unroll
    for (int im = 0; im < 4; im++)
        #pragma unroll
        for (int in = 0; in < 8; in++) {
            int r = wm + im * 16 + (lane >> 2);
            int cc = wn + in * 8 + (lane & 3) * 2;
            fs[r * 132 + cc]           = acc[im][in][0];
            fs[r * 132 + cc + 1]       = acc[im][in][1];
            fs[(r + 8) * 132 + cc]     = acc[im][in][2];
            fs[(r + 8) * 132 + cc + 1] = acc[im][in][3];
        }
    __syncthreads();

    if (mode <= 1) {
        for (int i = tid; i < 256 * 128; i += 256) {
            int r = i >> 7, cc = i & 127;
            float v = fs[r * 132 + cc] + bias[col0 + cc];
            size_t o = (size_t)(row0 + r) * HH + col0 + cc;
            if (mode == 0) Cf[o] = v;
            else Chi[o] = __float2half_rn(v);
        }
    } else {
        #pragma unroll
        for (int u = tid; u < 512; u += 256) {
            int r = u >> 1, g = u & 1;
            int cb = g * 64;
            float mx = -1e30f;
            #pragma unroll
            for (int m = 0; m < 64; m++)
                mx = fmaxf(mx, fs[r * 132 + cb + m] + bias[col0 + cb + m]);
            int tok = row0 + r;
            if (mode == 2) {
                size_t ob = (size_t)tok * HH + col0 + cb;
                for (int m = 0; m < 64; m++) {
                    float e = __expf(fs[r * 132 + cb + m] + bias[col0 + cb + m] - mx);
                    Chi[ob + m] = __float2half_rn(e);
                }
            } else {
                int b = tok >> 13, s = tok & (SS - 1);
                int h = (col0 + cb) >> 6;
                size_t ob = ((size_t)(b * NH + h) * SS + s) * MM;
                for (int m = 0; m < 64; m++) {
                    float e = __expf(fs[r * 132 + cb + m] + bias[col0 + cb + m] - mx);
                    Chi[ob + m] = __float2half_rn(e);
                }
            }
        }
    }
}

// ======================= qkv GEMM + normalize (N=80, fp16 1-pass) =======================
#define QA_HI 0
#define QB_HI 16384

__global__ __launch_bounds__(256, 1)
void qkv_tc_kernel(const __half* __restrict__ QPhi,
                   const __half* __restrict__ KVhi,
                   __half* __restrict__ Chi) {
    extern __shared__ char smem[];
    uint32_t sb = smem_u32(smem);
    int tid = threadIdx.x, wid = tid >> 5, lane = tid & 31;
    int bh = blockIdx.y, b = bh / NH, h = bh % NH;
    int s0 = blockIdx.x * 128;
    int row0 = b * SS + s0;
    int wm = (wid >> 1) * 32;          // 4 m-groups of 32
    int wn = (wid & 1) * 32;           // 2 n-groups of 32
    int has_x = (wid & 1);             // n-group 1 also owns cols 64-79

    cp_tile64(QPhi + h * 64, row0, HH, 0, sb + QA_HI, tid, 128);
    cp_tile64(KVhi + (size_t)bh * 128 * 64, 0, 64, 0, sb + QB_HI, tid, 80);
    CP_COMMIT();
    CP_WAIT0();
    __syncthreads();

    float acc[2][4][4];
    float accx[2][4];
    #pragma unroll
    for (int a = 0; a < 2; a++) {
        #pragma unroll
        for (int bq = 0; bq < 4; bq++)
            #pragma unroll
            for (int cq = 0; cq < 4; cq++) acc[a][bq][cq] = 0.f;
        #pragma unroll
        for (int cq = 0; cq < 4; cq++) accx[a][cq] = 0.f;
    }

    #pragma unroll
    for (int ks = 0; ks < 4; ks++) {
        uint32_t bh2[2][4], bxh[4];
        int kb = ks * 32 + ((lane & 8) ? 16 : 0);
        #pragma unroll
        for (int half = 0; half < 2; half++) {
            int nr = wn + half * 16 + (lane & 7) + ((lane & 16) ? 8 : 0);
            ldsm4(bh2[half], sb + QB_HI + SWZ((uint32_t)(nr * 128 + kb)));
        }
        if (has_x) {
            int nr = 64 + (lane & 7) + ((lane & 16) ? 8 : 0);
            ldsm4(bxh, sb + QB_HI + SWZ((uint32_t)(nr * 128 + kb)));
        }
        #pragma unroll
        for (int im = 0; im < 2; im++) {
            int rowa = wm + im * 16 + (lane & 15);
            int ka = ks * 32 + ((lane & 16) ? 16 : 0);
            uint32_t ah[4];
            ldsm4(ah, sb + QA_HI + SWZ((uint32_t)(rowa * 128 + ka)));
            #pragma unroll
            for (int in = 0; in < 4; in++) {
                const uint32_t* bhp = &bh2[in >> 1][(in & 1) * 2];
                mma16816(acc[im][in], ah, bhp);
            }
            if (has_x) mma16816(accx[im], ah, &bxh[0]);
        }
    }
    __syncthreads();

    float* fs = reinterpret_cast<float*>(smem);
    #pragma unroll
    for (int im = 0; im < 2; im++) {
        int r = wm + im * 16 + (lane >> 2);
        #pragma unroll
        for (int in = 0; in < 4; in++) {
            int cc = wn + in * 8 + (lane & 3) * 2;
            fs[r * 84 + cc]           = acc[im][in][0];
            fs[r * 84 + cc + 1]       = acc[im][in][1];
            fs[(r + 8) * 84 + cc]     = acc[im][in][2];
            fs[(r + 8) * 84 + cc + 1] = acc[im][in][3];
        }
        if (has_x) {
            int cc = 64 + (lane & 3) * 2;
            fs[r * 84 + cc]           = accx[im][0];
            fs[r * 84 + cc + 1]       = accx[im][1];
            fs[(r + 8) * 84 + cc]     = accx[im][2];
            fs[(r + 8) * 84 + cc + 1] = accx[im][3];
        }
    }
    __syncthreads();

    for (int i = tid; i < 128 * 64; i += 256) {
        int r = i >> 6, d = i & 63;
        float inv = 1.0f / (fs[r * 84 + 64] + EPSF);
        float v = fs[r * 84 + d] * inv;
        size_t o = (size_t)(row0 + r) * HH + h * HD + d;
        Chi[o] = __float2half_rn(v);
    }
}

// ======================= kv summary (SIMT, fp16 inputs, fp32 accum) =======================
#define KV_SPLITS 32
#define KV_ROWS (SS / KV_SPLITS)   // 256
#define KV_CH 32

__global__ __launch_bounds__(256)
void kv_accum_kernel(const __half* __restrict__ kp,   // [BHS, SS, MM]
                     const __half* __restrict__ v,    // [NTOK, HH] head cols
                     float* __restrict__ kv,          // [BHS, MM, HD]
                     float* __restrict__ ksum) {      // [BHS, MM]
    int bh = blockIdx.y;
    int b = bh / NH, h = bh % NH;
    int split = blockIdx.x;
    int tid = threadIdx.x;
    int m = tid & 63;
    int dg = tid >> 6;               // 0..3

    __shared__ __half kps[KV_CH][64];
    __shared__ __half vs[KV_CH][64];

    float acc[16] = {};
    float ks = 0.f;
    int n0 = split * KV_ROWS;

    for (int c0 = 0; c0 < KV_ROWS; c0 += KV_CH) {
        // per row: 64 halves = 8 x uint4(16B); KV_CH*8 = 256 loads per array
        {
            int i = tid;
            int r = i >> 3, c8 = i & 7;
            int n = n0 + c0 + r;
            *reinterpret_cast<uint4*>(&kps[r][c8 * 8]) =
                *reinterpret_cast<const uint4*>(kp + ((size_t)bh * SS + n) * MM + c8 * 8);
            *reinterpret_cast<uint4*>(&vs[r][c8 * 8]) =
                *reinterpret_cast<const uint4*>(v + ((size_t)(b * SS + n)) * HH + h * HD + c8 * 8);
        }
        __syncthreads();
        #pragma unroll
        for (int r = 0; r < KV_CH; r++) {
            float a = __half2float(kps[r][m]);
            if (dg == 0) ks += a;
            const __half2* vp = reinterpret_cast<const __half2*>(&vs[r][dg * 16]);
            #pragma unroll
            for (int j2 = 0; j2 < 8; j2++) {
                float2 vv = __half22float2(vp[j2]);
                acc[j2 * 2 + 0] = fmaf(a, vv.x, acc[j2 * 2 + 0]);
                acc[j2 * 2 + 1] = fmaf(a, vv.y, acc[j2 * 2 + 1]);
            }
        }
        __syncthreads();
    }

    float* kvp = kv + ((size_t)bh * MM + m) * HD + dg * 16;
    #pragma unroll
    for (int j = 0; j < 16; j++) atomicAdd(&kvp[j], acc[j]);
    if (dg == 0) atomicAdd(&ksum[(size_t)bh * MM + m], ks);
}

// ======================= launch =======================
extern "C" void kernel_launch(void* const* d_in, const int* in_sizes, int n_in,
                              void* d_out, int out_size) {
    const float* X  = (const float*)d_in[0];
    const float* Wq = (const float*)d_in[1];
    const float* bq = (const float*)d_in[2];
    const float* Wk = (const float*)d_in[3];
    const float* bk = (const float*)d_in[4];
    const float* Wv = (const float*)d_in[5];
    const float* bv = (const float*)d_in[6];
    const float* Wo = (const float*)d_in[7];
    const float* bo = (const float*)d_in[8];
    const float* P  = (const float*)d_in[9];
    float* out = (float*)d_out;

    __half *xhi, *xlo, *wqph, *wkph, *wvth, *woth;
    __half *qphi, *kph, *vh, *kvxh, *ctxh;
    float *bqf, *bkf, *kvf, *ksum;
    cudaGetSymbolAddress((void**)&xhi, g_xhi);   cudaGetSymbolAddress((void**)&xlo, g_xlo);
    cudaGetSymbolAddress((void**)&wqph, g_wqph);
    cudaGetSymbolAddress((void**)&wkph, g_wkph);
    cudaGetSymbolAddress((void**)&wvth, g_wvth);
    cudaGetSymbolAddress((void**)&woth, g_woth);
    cudaGetSymbolAddress((void**)&bqf, g_bqf);   cudaGetSymbolAddress((void**)&bkf, g_bkf);
    cudaGetSymbolAddress((void**)&qphi, g_qphi);
    cudaGetSymbolAddress((void**)&kph, g_kph);   cudaGetSymbolAddress((void**)&vh, g_vh);
    cudaGetSymbolAddress((void**)&kvf, g_kv);    cudaGetSymbolAddress((void**)&ksum, g_ksum);
    cudaGetSymbolAddress((void**)&kvxh, g_kvxh);
    cudaGetSymbolAddress((void**)&ctxh, g_ctxh);

    cudaFuncSetAttribute(gemm_tc_kernel<2>, cudaFuncAttributeMaxDynamicSharedMemorySize, 163840);
    cudaFuncSetAttribute(gemm_tc_kernel<1>, cudaFuncAttributeMaxDynamicSharedMemorySize, 163840);
    cudaFuncSetAttribute(qkv_tc_kernel,  cudaFuncAttributeMaxDynamicSharedMemorySize, 49152);

    // preprocessing
    split_f32_kernel<<<2048, 256>>>(X, xhi, xlo, (size_t)NTOK * HH / 2);
    dim3 wtg(HH / 32, HH / 32, 2);
    wt_prep_kernel<<<wtg, dim3(32, 8)>>>(Wv, Wo, wvth, woth);
    dim3 fwg(HH / 64, NH);
    fold_w_kernel<<<fwg, 256>>>(Wq, P, wqph);
    fold_w_kernel<<<fwg, 256>>>(Wk, P, wkph);
    fold_b_kernel<<<dim3(NH, 2), 64>>>(bq, bk, P, bqf, bkf);

    dim3 gg(HH / 128, NTOK / 256);    // (6, 128)
    // qp = exp(X@Wqp + bqf - rowmax)  (fp16, [tok][768]) — 2-pass (feeds per-row output)
    gemm_tc_kernel<2><<<gg, 256, 163840>>>(xhi, xlo, wqph, bqf, nullptr, qphi, 2);
    // kp = exp(X@Wkp + bkf - rowmax)  (fp16, [bh][s][64]) — 1-pass (errors average in kv sum)
    gemm_tc_kernel<1><<<gg, 256, 163840>>>(xhi, xlo, wkph, bkf, nullptr, kph, 3);
    // v = X@Wv + bv  (fp16) — 1-pass
    gemm_tc_kernel<1><<<gg, 256, 163840>>>(xhi, xlo, wvth, bv, nullptr, vh, 1);

    // kv summary
    zero_kernel<<<(BHS * MM * HD + 255) / 256, 256>>>(kvf, BHS * MM * HD);
    zero_kernel<<<(BHS * MM + 255) / 256, 256>>>(ksum, BHS * MM);
    dim3 kvg(KV_SPLITS, BHS);
    kv_accum_kernel<<<kvg, 256>>>(kph, vh, kvf, ksum);
    kvx_prep_kernel<<<BHS, 256>>>(kvf, ksum, kvxh);

    // recombine + normalize -> ctx fp16 (1-pass)
    dim3 pg(SS / 128, BHS);           // (64, 48)
    qkv_tc_kernel<<<pg, 256, 49152>>>(qphi, kvxh, ctxh);

    // out = ctx@Wo + bo (fp32) — 1-pass
    gemm_tc_kernel<1><<<gg, 256, 163840>>>(ctxh, xlo, woth, bo, out, nullptr, 0);
}

// round 17
// speedup vs baseline: 1.7069x; 1.7069x over previous
#include <cuda_runtime.h>
#include <cuda_fp16.h>
#include <cstdint>
#include <math.h>

#define BB 4
#define SS 8192
#define HH 768
#define NH 12
#define HD 64
#define MM 64
#define NTOK (BB * SS)          // 32768
#define BHS (BB * NH)           // 48
#define EPSF 1e-6f

// ======================= helpers =======================
__device__ __forceinline__ uint32_t smem_u32(const void* p) {
    uint32_t a;
    asm("{ .reg .u64 t; cvta.to.shared.u64 t, %1; cvt.u32.u64 %0, t; }" : "=r"(a) : "l"(p));
    return a;
}

#define SWZ(o) ((o) ^ (((o) >> 3) & 0x70))

__device__ __forceinline__ void cpa16(uint32_t dst, const void* src) {
    asm volatile("cp.async.cg.shared.global [%0], [%1], 16;" :: "r"(dst), "l"(src));
}
#define CP_COMMIT() asm volatile("cp.async.commit_group;" ::: "memory")
#define CP_WAIT0()  asm volatile("cp.async.wait_group 0;" ::: "memory")
#define CP_WAIT1()  asm volatile("cp.async.wait_group 1;" ::: "memory")

__device__ __forceinline__ void ldsm4(uint32_t* r, uint32_t addr) {
    asm volatile("ldmatrix.sync.aligned.m8n8.x4.shared.b16 {%0,%1,%2,%3}, [%4];"
        : "=r"(r[0]), "=r"(r[1]), "=r"(r[2]), "=r"(r[3]) : "r"(addr));
}
// fp16 MMA, f32 accumulate
__device__ __forceinline__ void mma16816(float* c, const uint32_t* a, const uint32_t* b) {
    asm volatile("mma.sync.aligned.m16n8k16.row.col.f32.f16.f16.f32 "
        "{%0,%1,%2,%3}, {%4,%5,%6,%7}, {%8,%9}, {%0,%1,%2,%3};"
        : "+f"(c[0]), "+f"(c[1]), "+f"(c[2]), "+f"(c[3])
        : "r"(a[0]), "r"(a[1]), "r"(a[2]), "r"(a[3]), "r"(b[0]), "r"(b[1]));
}

__device__ __forceinline__ void split2(float v, __half& hi, __half& lo) {
    hi = __float2half_rn(v);
    lo = __float2half_rn(v - __half2float(hi));
}

// load a [rows x 64] half chunk (row -> 128B swizzled) via cp.async
__device__ __forceinline__ void cp_tile64(const __half* __restrict__ g, int row0,
                                          int ld, int kc0, uint32_t sbase, int tid, int rows) {
    int total = rows * 8;
    for (int i = tid; i < total; i += 256) {
        int r = i >> 3, j = i & 7;
        uint32_t bo = (uint32_t)(r * 128 + j * 16);
        cpa16(sbase + SWZ(bo), g + (size_t)(row0 + r) * ld + kc0 + j * 8);
    }
}

// ======================= scratch =======================
__device__ __half g_xhi[(size_t)NTOK * HH], g_xlo[(size_t)NTOK * HH];
__device__ __half g_wqph[(size_t)HH * HH];
__device__ __half g_wkph[(size_t)HH * HH];
__device__ __half g_wvth[(size_t)HH * HH];
__device__ __half g_woth[(size_t)HH * HH];
__device__ float  g_bqf[HH], g_bkf[HH];
__device__ __half g_qphi[(size_t)NTOK * HH];
__device__ float  g_kpf[(size_t)BHS * SS * MM];
__device__ float  g_v[(size_t)NTOK * HH];
__device__ float  g_kv[(size_t)BHS * MM * HD];
__device__ float  g_ksum[(size_t)BHS * MM];
__device__ __half g_kvxh[(size_t)BHS * 128 * 64];
__device__ __half g_ctxh[(size_t)NTOK * HH];

// ======================= preprocessing =======================
__global__ void split_f32_kernel(const float* __restrict__ x,
                                 __half* __restrict__ hi,
                                 __half* __restrict__ lo, size_t n2) {
    const float2* x2 = reinterpret_cast<const float2*>(x);
    __half2* h2 = reinterpret_cast<__half2*>(hi);
    __half2* l2 = reinterpret_cast<__half2*>(lo);
    for (size_t i = (size_t)blockIdx.x * blockDim.x + threadIdx.x; i < n2;
         i += (size_t)gridDim.x * blockDim.x) {
        float2 v = x2[i];
        __half hx, lx, hy, ly;
        split2(v.x, hx, lx);
        split2(v.y, hy, ly);
        h2[i] = __half2(hx, hy);
        l2[i] = __half2(lx, ly);
    }
}

// W[K=768][N=768] -> Wt[n][k] fp16 hi; z selects (Wv, Wo)
__global__ void wt_prep_kernel(const float* __restrict__ Wv, const float* __restrict__ Wo,
                               __half* __restrict__ hiV, __half* __restrict__ hiO) {
    const float* W = blockIdx.z ? Wo : Wv;
    __half* hi = blockIdx.z ? hiO : hiV;
    __shared__ float t[32][33];
    int bx = blockIdx.x * 32, by = blockIdx.y * 32;
    int x = threadIdx.x, y = threadIdx.y;   // block (32,8)
    #pragma unroll
    for (int i = 0; i < 32; i += 8)
        t[y + i][x] = W[(size_t)(by + y + i) * HH + bx + x];
    __syncthreads();
    #pragma unroll
    for (int i = 0; i < 32; i += 8) {
        size_t o = (size_t)(bx + y + i) * HH + by + x;
        hi[o] = __float2half_rn(t[x][y + i]);
    }
}

// Wt_fold[n=h*64+m][k=i] = sum_d W[i][h*64+d] * P[h][d][m]; 64 i-rows per block
__global__ void fold_w_kernel(const float* __restrict__ W, const float* __restrict__ P,
                              __half* __restrict__ hi) {
    int h = blockIdx.y;
    int i0 = blockIdx.x * 64;
    __shared__ float Ps[64][65];
    __shared__ float Ws[64][65];
    for (int t = threadIdx.x; t < 64 * 64; t += 256) {
        Ps[t >> 6][t & 63] = P[(size_t)h * 4096 + t];
        Ws[t >> 6][t & 63] = W[(size_t)(i0 + (t >> 6)) * HH + h * 64 + (t & 63)];
    }
    __syncthreads();
    for (int t = threadIdx.x; t < 64 * 64; t += 256) {
        int il = t >> 6, m = t & 63;
        float s = 0.f;
        #pragma unroll
        for (int d = 0; d < 64; d++) s = fmaf(Ws[il][d], Ps[d][m], s);
        hi[(size_t)(h * 64 + m) * HH + i0 + il] = __float2half_rn(s);
    }
}

// b_fold[h*64+m] = sum_d b[h*64+d] * P[h][d][m]; y selects (bq, bk)
__global__ void fold_b_kernel(const float* __restrict__ bq, const float* __restrict__ bk,
                              const float* __restrict__ P,
                              float* __restrict__ bqo, float* __restrict__ bko) {
    const float* b = blockIdx.y ? bk : bq;
    float* bout = blockIdx.y ? bko : bqo;
    int h = blockIdx.x, m = threadIdx.x;
    float s = 0.f;
    for (int d = 0; d < 64; d++)
        s = fmaf(b[h * 64 + d], P[(size_t)h * 4096 + d * 64 + m], s);
    bout[h * 64 + m] = s;
}

// kv [bh][m][d], ksum [bh][m] -> kvx [bh][n][k] (80 rows): n<64: kv[k][n]; n==64: ksum[k]; 65..79: 0
__global__ void kvx_prep_kernel(const float* __restrict__ kvf,
                                const float* __restrict__ ksum,
                                __half* __restrict__ hi) {
    int bh = blockIdx.x;
    for (int i = threadIdx.x; i < 80 * 64; i += 256) {
        int n = i >> 6, kk = i & 63;
        float v = 0.f;
        if (n < 64)       v = kvf[((size_t)bh * MM + kk) * HD + n];
        else if (n == 64) v = ksum[(size_t)bh * MM + kk];
        hi[(size_t)bh * 128 * 64 + i] = __float2half_rn(v);
    }
}

__global__ void zero_kernel(float* __restrict__ p, int n) {
    int i = blockIdx.x * blockDim.x + threadIdx.x;
    if (i < n) p[i] = 0.f;
}

// ======================= big GEMM: 256x128 CTA tile, 64x64 warp tile =======================
// NPASS=2: (a_hi + a_lo) * b_hi ; NPASS=1: a_hi * b_hi
// mode 0: fp32 + bias -> Cf.  mode 1: fp16 + bias -> Chi.
// mode 2: exp(...) fp16 -> Chi [tok][768].  mode 3: exp(...) fp32 -> Cf kp layout [bh][s][64].
#define SA_HI 0
#define SA_LO 32768
#define SB_HI 65536
#define STAGE 81920

template <int NPASS>
__global__ __launch_bounds__(256, 1)
void gemm_tc_kernel(const __half* __restrict__ Ahi, const __half* __restrict__ Alo,
                    const __half* __restrict__ Bhi,
                    const float* __restrict__ bias, float* __restrict__ Cf,
                    __half* __restrict__ Chi, int mode) {
    extern __shared__ char smem[];
    uint32_t sb = smem_u32(smem);
    int tid = threadIdx.x, wid = tid >> 5, lane = tid & 31;
    int row0 = blockIdx.y * 256, col0 = blockIdx.x * 128;
    int wm = (wid & 3) * 64, wn = (wid >> 2) * 64;

    float acc[4][8][4];
    #pragma unroll
    for (int a = 0; a < 4; a++)
        #pragma unroll
        for (int bq = 0; bq < 8; bq++)
            #pragma unroll
            for (int cq = 0; cq < 4; cq++) acc[a][bq][cq] = 0.f;

    // prologue: stage 0
    {
        cp_tile64(Ahi, row0, HH, 0, sb + SA_HI, tid, 256);
        if (NPASS == 2) cp_tile64(Alo, row0, HH, 0, sb + SA_LO, tid, 256);
        cp_tile64(Bhi, col0, HH, 0, sb + SB_HI, tid, 128);
        CP_COMMIT();
    }

    for (int c = 0; c < 12; c++) {
        int buf = c & 1;
        if (c + 1 < 12) {
            uint32_t sn = sb + (buf ^ 1) * STAGE;
            int kc = (c + 1) * 64;
            cp_tile64(Ahi, row0, HH, kc, sn + SA_HI, tid, 256);
            if (NPASS == 2) cp_tile64(Alo, row0, HH, kc, sn + SA_LO, tid, 256);
            cp_tile64(Bhi, col0, HH, kc, sn + SB_HI, tid, 128);
            CP_COMMIT();
            CP_WAIT1();
        } else {
            CP_WAIT0();
        }
        __syncthreads();

        uint32_t s0 = sb + buf * STAGE;
        #pragma unroll
        for (int ks = 0; ks < 4; ks++) {
            uint32_t bh2[4][4];
            int kb = ks * 32 + ((lane & 8) ? 16 : 0);
            #pragma unroll
            for (int q = 0; q < 4; q++) {
                int nr = wn + q * 16 + (lane & 7) + ((lane & 16) ? 8 : 0);
                ldsm4(bh2[q], s0 + SB_HI + SWZ((uint32_t)(nr * 128 + kb)));
            }
            #pragma unroll
            for (int im = 0; im < 4; im++) {
                int rowa = wm + im * 16 + (lane & 15);
                int ka = ks * 32 + ((lane & 16) ? 16 : 0);
                uint32_t ah[4], al[4];
                ldsm4(ah, s0 + SA_HI + SWZ((uint32_t)(rowa * 128 + ka)));
                if (NPASS == 2) ldsm4(al, s0 + SA_LO + SWZ((uint32_t)(rowa * 128 + ka)));
                #pragma unroll
                for (int in = 0; in < 8; in++) {
                    const uint32_t* bhp = &bh2[in >> 1][(in & 1) * 2];
                    mma16816(acc[im][in], ah, bhp);
                    if (NPASS == 2) mma16816(acc[im][in], al, bhp);
                }
            }
        }
        __syncthreads();
    }

    // stage accumulators to smem (256 x 128, stride 132)
    float* fs = reinterpret_cast<float*>(smem);
    #pragma unroll
    for (int im = 0; im < 4; im++)
        #pragma unroll
        for (int in = 0; in < 8; in++) {
            int r = wm + im * 16 + (lane >> 2);
            int cc = wn + in * 8 + (lane & 3) * 2;
            fs[r * 132 + cc]           = acc[im][in][0];
            fs[r * 132 + cc + 1]       = acc[im][in][1];
            fs[(r + 8) * 132 + cc]     = acc[im][in][2];
            fs[(r + 8) * 132 + cc + 1] = acc[im][in][3];
        }
    __syncthreads();

    if (mode <= 1) {
        for (int i = tid; i < 256 * 128; i += 256) {
            int r = i >> 7, cc = i & 127;
            float v = fs[r * 132 + cc] + bias[col0 + cc];
            size_t o = (size_t)(row0 + r) * HH + col0 + cc;
            if (mode == 0) Cf[o] = v;
            else Chi[o] = __float2half_rn(v);
        }
    } else {
        #pragma unroll
        for (int u = tid; u < 512; u += 256) {
            int r = u >> 1, g = u & 1;
            int cb = g * 64;
            float mx = -1e30f;
            #pragma unroll
            for (int m = 0; m < 64; m++)
                mx = fmaxf(mx, fs[r * 132 + cb + m] + bias[col0 + cb + m]);
            int tok = row0 + r;
            if (mode == 2) {
                size_t ob = (size_t)tok * HH + col0 + cb;
                for (int m = 0; m < 64; m++) {
                    float e = __expf(fs[r * 132 + cb + m] + bias[col0 + cb + m] - mx);
                    Chi[ob + m] = __float2half_rn(e);
                }
            } else {
                int b = tok >> 13, s = tok & (SS - 1);
                int h = (col0 + cb) >> 6;
                size_t ob = ((size_t)(b * NH + h) * SS + s) * MM;
                for (int m = 0; m < 64; m++)
                    Cf[ob + m] = __expf(fs[r * 132 + cb + m] + bias[col0 + cb + m] - mx);
            }
        }
    }
}

// ======================= qkv GEMM + normalize (N=80, fp16 1-pass) =======================
#define QA_HI 0
#define QB_HI 16384

__global__ __launch_bounds__(256, 1)
void qkv_tc_kernel(const __half* __restrict__ QPhi,
                   const __half* __restrict__ KVhi,
                   __half* __restrict__ Chi) {
    extern __shared__ char smem[];
    uint32_t sb = smem_u32(smem);
    int tid = threadIdx.x, wid = tid >> 5, lane = tid & 31;
    int bh = blockIdx.y, b = bh / NH, h = bh % NH;
    int s0 = blockIdx.x * 128;
    int row0 = b * SS + s0;
    int wm = (wid >> 1) * 32;          // 4 m-groups of 32
    int wn = (wid & 1) * 32;           // 2 n-groups of 32
    int has_x = (wid & 1);             // n-group 1 also owns cols 64-79

    cp_tile64(QPhi + h * 64, row0, HH, 0, sb + QA_HI, tid, 128);
    cp_tile64(KVhi + (size_t)bh * 128 * 64, 0, 64, 0, sb + QB_HI, tid, 80);
    CP_COMMIT();
    CP_WAIT0();
    __syncthreads();

    float acc[2][4][4];
    float accx[2][4];
    #pragma unroll
    for (int a = 0; a < 2; a++) {
        #pragma unroll
        for (int bq = 0; bq < 4; bq++)
            #pragma unroll
            for (int cq = 0; cq < 4; cq++) acc[a][bq][cq] = 0.f;
        #pragma unroll
        for (int cq = 0; cq < 4; cq++) accx[a][cq] = 0.f;
    }

    #pragma unroll
    for (int ks = 0; ks < 4; ks++) {
        uint32_t bh2[2][4], bxh[4];
        int kb = ks * 32 + ((lane & 8) ? 16 : 0);
        #pragma unroll
        for (int half = 0; half < 2; half++) {
            int nr = wn + half * 16 + (lane & 7) + ((lane & 16) ? 8 : 0);
            ldsm4(bh2[half], sb + QB_HI + SWZ((uint32_t)(nr * 128 + kb)));
        }
        if (has_x) {
            int nr = 64 + (lane & 7) + ((lane & 16) ? 8 : 0);
            ldsm4(bxh, sb + QB_HI + SWZ((uint32_t)(nr * 128 + kb)));
        }
        #pragma unroll
        for (int im = 0; im < 2; im++) {
            int rowa = wm + im * 16 + (lane & 15);
            int ka = ks * 32 + ((lane & 16) ? 16 : 0);
            uint32_t ah[4];
            ldsm4(ah, sb + QA_HI + SWZ((uint32_t)(rowa * 128 + ka)));
            #pragma unroll
            for (int in = 0; in < 4; in++) {
                const uint32_t* bhp = &bh2[in >> 1][(in & 1) * 2];
                mma16816(acc[im][in], ah, bhp);
            }
            if (has_x) mma16816(accx[im], ah, &bxh[0]);
        }
    }
    __syncthreads();

    float* fs = reinterpret_cast<float*>(smem);
    #pragma unroll
    for (int im = 0; im < 2; im++) {
        int r = wm + im * 16 + (lane >> 2);
        #pragma unroll
        for (int in = 0; in < 4; in++) {
            int cc = wn + in * 8 + (lane & 3) * 2;
            fs[r * 84 + cc]           = acc[im][in][0];
            fs[r * 84 + cc + 1]       = acc[im][in][1];
            fs[(r + 8) * 84 + cc]     = acc[im][in][2];
            fs[(r + 8) * 84 + cc + 1] = acc[im][in][3];
        }
        if (has_x) {
            int cc = 64 + (lane & 3) * 2;
            fs[r * 84 + cc]           = accx[im][0];
            fs[r * 84 + cc + 1]       = accx[im][1];
            fs[(r + 8) * 84 + cc]     = accx[im][2];
            fs[(r + 8) * 84 + cc + 1] = accx[im][3];
        }
    }
    __syncthreads();

    for (int i = tid; i < 128 * 64; i += 256) {
        int r = i >> 6, d = i & 63;
        float inv = 1.0f / (fs[r * 84 + 64] + EPSF);
        float v = fs[r * 84 + d] * inv;
        size_t o = (size_t)(row0 + r) * HH + h * HD + d;
        Chi[o] = __float2half_rn(v);
    }
}

// ======================= kv summary (SIMT, float4-vectorized, fp32) =======================
#define KV_SPLITS 32
#define KV_ROWS (SS / KV_SPLITS)   // 256
#define KV_CH 32

__global__ __launch_bounds__(256)
void kv_accum_kernel(const float* __restrict__ kp,   // [BHS, SS, MM]
                     const float* __restrict__ v,    // [NTOK, HH]
                     float* __restrict__ kv,         // [BHS, MM, HD]
                     float* __restrict__ ksum) {     // [BHS, MM]
    int bh = blockIdx.y;
    int b = bh / NH, h = bh % NH;
    int split = blockIdx.x;
    int tid = threadIdx.x;
    int m = tid & 63;
    int dg = tid >> 6;               // 0..3

    __shared__ float4 kps4[KV_CH][16];
    __shared__ float4 vs4[KV_CH][16];

    float acc[16] = {};
    float ks = 0.f;
    int n0 = split * KV_ROWS;

    for (int c0 = 0; c0 < KV_ROWS; c0 += KV_CH) {
        #pragma unroll
        for (int i = tid; i < KV_CH * 16; i += 256) {
            int r = i >> 4, c4 = i & 15;
            int n = n0 + c0 + r;
            kps4[r][c4] = *reinterpret_cast<const float4*>(kp + ((size_t)bh * SS + n) * MM + c4 * 4);
            vs4[r][c4]  = *reinterpret_cast<const float4*>(v + ((size_t)(b * SS + n)) * HH + h * HD + c4 * 4);
        }
        __syncthreads();
        #pragma unroll
        for (int r = 0; r < KV_CH; r++) {
            float a = reinterpret_cast<const float*>(&kps4[r][0])[m];
            if (dg == 0) ks += a;
            #pragma unroll
            for (int j4 = 0; j4 < 4; j4++) {
                float4 vv = vs4[r][dg * 4 + j4];
                acc[j4 * 4 + 0] = fmaf(a, vv.x, acc[j4 * 4 + 0]);
                acc[j4 * 4 + 1] = fmaf(a, vv.y, acc[j4 * 4 + 1]);
                acc[j4 * 4 + 2] = fmaf(a, vv.z, acc[j4 * 4 + 2]);
                acc[j4 * 4 + 3] = fmaf(a, vv.w, acc[j4 * 4 + 3]);
            }
        }
        __syncthreads();
    }

    float* kvp = kv + ((size_t)bh * MM + m) * HD + dg * 16;
    #pragma unroll
    for (int j = 0; j < 16; j++) atomicAdd(&kvp[j], acc[j]);
    if (dg == 0) atomicAdd(&ksum[(size_t)bh * MM + m], ks);
}

// ======================= launch =======================
extern "C" void kernel_launch(void* const* d_in, const int* in_sizes, int n_in,
                              void* d_out, int out_size) {
    const float* X  = (const float*)d_in[0];
    const float* Wq = (const float*)d_in[1];
    const float* bq = (const float*)d_in[2];
    const float* Wk = (const float*)d_in[3];
    const float* bk = (const float*)d_in[4];
    const float* Wv = (const float*)d_in[5];
    const float* bv = (const float*)d_in[6];
    const float* Wo = (const float*)d_in[7];
    const float* bo = (const float*)d_in[8];
    const float* P  = (const float*)d_in[9];
    float* out = (float*)d_out;

    __half *xhi, *xlo, *wqph, *wkph, *wvth, *woth;
    __half *qphi, *kvxh, *ctxh;
    float *bqf, *bkf, *vf, *kpf, *kvf, *ksum;
    cudaGetSymbolAddress((void**)&xhi, g_xhi);   cudaGetSymbolAddress((void**)&xlo, g_xlo);
    cudaGetSymbolAddress((void**)&wqph, g_wqph);
    cudaGetSymbolAddress((void**)&wkph, g_wkph);
    cudaGetSymbolAddress((void**)&wvth, g_wvth);
    cudaGetSymbolAddress((void**)&woth, g_woth);
    cudaGetSymbolAddress((void**)&bqf, g_bqf);   cudaGetSymbolAddress((void**)&bkf, g_bkf);
    cudaGetSymbolAddress((void**)&qphi, g_qphi);
    cudaGetSymbolAddress((void**)&kpf, g_kpf);   cudaGetSymbolAddress((void**)&vf, g_v);
    cudaGetSymbolAddress((void**)&kvf, g_kv);    cudaGetSymbolAddress((void**)&ksum, g_ksum);
    cudaGetSymbolAddress((void**)&kvxh, g_kvxh);
    cudaGetSymbolAddress((void**)&ctxh, g_ctxh);

    cudaFuncSetAttribute(gemm_tc_kernel<2>, cudaFuncAttributeMaxDynamicSharedMemorySize, 163840);
    cudaFuncSetAttribute(gemm_tc_kernel<1>, cudaFuncAttributeMaxDynamicSharedMemorySize, 163840);
    cudaFuncSetAttribute(qkv_tc_kernel,  cudaFuncAttributeMaxDynamicSharedMemorySize, 49152);

    // preprocessing
    split_f32_kernel<<<2048, 256>>>(X, xhi, xlo, (size_t)NTOK * HH / 2);
    dim3 wtg(HH / 32, HH / 32, 2);
    wt_prep_kernel<<<wtg, dim3(32, 8)>>>(Wv, Wo, wvth, woth);
    dim3 fwg(HH / 64, NH);
    fold_w_kernel<<<fwg, 256>>>(Wq, P, wqph);
    fold_w_kernel<<<fwg, 256>>>(Wk, P, wkph);
    fold_b_kernel<<<dim3(NH, 2), 64>>>(bq, bk, P, bqf, bkf);

    dim3 gg(HH / 128, NTOK / 256);    // (6, 128)
    // qp = exp(X@Wqp + bqf - rowmax)  (fp16, [tok][768]) — 2-pass (errors hit outputs directly)
    gemm_tc_kernel<2><<<gg, 256, 163840>>>(xhi, xlo, wqph, bqf, nullptr, qphi, 2);
    // kp = exp(X@Wkp + bkf - rowmax)  (fp32, [bh][s][64]) — 1-pass (errors average over S in kv sum)
    gemm_tc_kernel<1><<<gg, 256, 163840>>>(xhi, xlo, wkph, bkf, kpf, nullptr, 3);
    // v = X@Wv + bv  (fp32) — 1-pass
    gemm_tc_kernel<1><<<gg, 256, 163840>>>(xhi, xlo, wvth, bv, vf, nullptr, 0);

    // kv summary
    zero_kernel<<<(BHS * MM * HD + 255) / 256, 256>>>(kvf, BHS * MM * HD);
    zero_kernel<<<(BHS * MM + 255) / 256, 256>>>(ksum, BHS * MM);
    dim3 kvg(KV_SPLITS, BHS);
    kv_accum_kernel<<<kvg, 256>>>(kpf, vf, kvf, ksum);
    kvx_prep_kernel<<<BHS, 256>>>(kvf, ksum, kvxh);

    // recombine + normalize -> ctx fp16 (1-pass)
    dim3 pg(SS / 128, BHS);           // (64, 48)
    qkv_tc_kernel<<<pg, 256, 49152>>>(qphi, kvxh, ctxh);

    // out = ctx@Wo + bo (fp32) — 1-pass
    gemm_tc_kernel<1><<<gg, 256, 163840>>>(ctxh, xlo, woth, bo, out, nullptr, 0);
}